// round 6
// baseline (speedup 1.0000x reference)
#include <cuda_runtime.h>

#define NUM_USERS 100000
#define N_NODES   300000
#define NNZ_E     1200000
#define DIM       64
#define OUT_COLS  256
#define TILE_N    64
#define SROW      68   // padded row stride (floats) for side/emb smem tiles

__device__ __align__(16) float g_emb[(size_t)N_NODES * DIM];
__device__ __align__(16) float g_side[(size_t)N_NODES * DIM];

// ---------------------------------------------------------------------------
// Copy concat(user_emb, item_emb) into g_emb and into d_out[:, 0:64],
// and zero g_side for the first SpMM.
// ---------------------------------------------------------------------------
__global__ void concat_kernel(const float* __restrict__ ue,
                              const float* __restrict__ ie,
                              float* __restrict__ out) {
    int idx = blockIdx.x * blockDim.x + threadIdx.x;   // float4 index
    const int total = N_NODES * (DIM / 4);
    if (idx >= total) return;
    int node = idx >> 4;        // /16
    int c4   = idx & 15;
    float4 v;
    if (node < NUM_USERS) v = ((const float4*)ue)[node * 16 + c4];
    else                  v = ((const float4*)ie)[(node - NUM_USERS) * 16 + c4];
    ((float4*)g_emb)[idx] = v;
    ((float4*)g_side)[idx] = make_float4(0.f, 0.f, 0.f, 0.f);
    ((float4*)out)[(size_t)node * (OUT_COLS / 4) + c4] = v;
}

// ---------------------------------------------------------------------------
// SpMM scatter: side[rows[e]] += vals[e] * emb[cols[e]]
// 16 threads per edge, each handles a float4 chunk, vectorized red.global
// ---------------------------------------------------------------------------
__global__ void spmm_kernel(const int* __restrict__ rows,
                            const int* __restrict__ cols,
                            const float* __restrict__ vals) {
    int idx = blockIdx.x * blockDim.x + threadIdx.x;
    if (idx >= NNZ_E * 16) return;
    int e = idx >> 4;
    int c = idx & 15;
    int r  = __ldg(&rows[e]);
    int cl = __ldg(&cols[e]);
    float v = __ldg(&vals[e]);
    float4 x = ((const float4*)g_emb)[(size_t)cl * 16 + c];
    float* dst = g_side + (size_t)r * DIM + c * 4;
    asm volatile("red.global.add.v4.f32 [%0], {%1, %2, %3, %4};"
                 :: "l"(dst), "f"(v * x.x), "f"(v * x.y), "f"(v * x.z), "f"(v * x.w)
                 : "memory");
}

// ---------------------------------------------------------------------------
// Dense: out = leaky_relu(side@Wc + bc + (side*emb)@We + be)
//   - writes unnormalized out back to g_emb (input to next layer)
//   - writes L2-normalized rows to d_out column slice
//   - re-zeroes its g_side tile so the next layer's SpMM scatters onto zeros
// Block: 256 threads, tile of 64 nodes x 64 dims. Thread owns 4 nodes x 4 dims.
// ---------------------------------------------------------------------------
extern __shared__ float smem[];

__global__ __launch_bounds__(256) void dense_kernel(
    const float* __restrict__ Wc, const float* __restrict__ bc,
    const float* __restrict__ We, const float* __restrict__ be,
    float* __restrict__ out_col /* = d_out + (l+1)*64 */)
{
    float* sWc = smem;                    // 64*64
    float* sWe = smem + 4096;             // 64*64
    float* sS  = smem + 8192;             // 64*SROW
    float* sE  = sS + TILE_N * SROW;      // 64*SROW

    int tid = threadIdx.x;
    int nb  = blockIdx.x * TILE_N;

    // Load weight matrices (row-major [k][j])
    for (int i = tid; i < 1024; i += 256) {
        ((float4*)sWc)[i] = ((const float4*)Wc)[i];
        ((float4*)sWe)[i] = ((const float4*)We)[i];
    }
    // Load side/emb tiles (zero-padded past N); zero g_side for next layer
    for (int i = tid; i < TILE_N * 16; i += 256) {
        int nl = i >> 4;
        int c4 = i & 15;
        int node = nb + nl;
        float4 s4 = make_float4(0.f, 0.f, 0.f, 0.f);
        float4 e4 = make_float4(0.f, 0.f, 0.f, 0.f);
        if (node < N_NODES) {
            s4 = ((const float4*)g_side)[(size_t)node * 16 + c4];
            e4 = ((const float4*)g_emb)[(size_t)node * 16 + c4];
            ((float4*)g_side)[(size_t)node * 16 + c4] = make_float4(0.f, 0.f, 0.f, 0.f);
        }
        *(float4*)&sS[nl * SROW + c4 * 4] = s4;
        *(float4*)&sE[nl * SROW + c4 * 4] = e4;
    }
    __syncthreads();

    int j4 = tid & 15;        // float4 chunk of output dim
    int ng = tid >> 4;        // node group (0..15)
    int n0 = ng * 4;

    float4 a0 = make_float4(0.f,0.f,0.f,0.f);
    float4 a1 = make_float4(0.f,0.f,0.f,0.f);
    float4 a2 = make_float4(0.f,0.f,0.f,0.f);
    float4 a3 = make_float4(0.f,0.f,0.f,0.f);

    #pragma unroll 4
    for (int k = 0; k < 64; k++) {
        float4 wc = *(const float4*)&sWc[k * 64 + j4 * 4];
        float4 we = *(const float4*)&sWe[k * 64 + j4 * 4];
        float s0 = sS[(n0+0)*SROW + k], e0 = sE[(n0+0)*SROW + k];
        float s1 = sS[(n0+1)*SROW + k], e1 = sE[(n0+1)*SROW + k];
        float s2 = sS[(n0+2)*SROW + k], e2 = sE[(n0+2)*SROW + k];
        float s3 = sS[(n0+3)*SROW + k], e3 = sE[(n0+3)*SROW + k];
        float p0 = s0 * e0, p1 = s1 * e1, p2 = s2 * e2, p3 = s3 * e3;
        a0.x = fmaf(s0, wc.x, fmaf(p0, we.x, a0.x));
        a0.y = fmaf(s0, wc.y, fmaf(p0, we.y, a0.y));
        a0.z = fmaf(s0, wc.z, fmaf(p0, we.z, a0.z));
        a0.w = fmaf(s0, wc.w, fmaf(p0, we.w, a0.w));
        a1.x = fmaf(s1, wc.x, fmaf(p1, we.x, a1.x));
        a1.y = fmaf(s1, wc.y, fmaf(p1, we.y, a1.y));
        a1.z = fmaf(s1, wc.z, fmaf(p1, we.z, a1.z));
        a1.w = fmaf(s1, wc.w, fmaf(p1, we.w, a1.w));
        a2.x = fmaf(s2, wc.x, fmaf(p2, we.x, a2.x));
        a2.y = fmaf(s2, wc.y, fmaf(p2, we.y, a2.y));
        a2.z = fmaf(s2, wc.z, fmaf(p2, we.z, a2.z));
        a2.w = fmaf(s2, wc.w, fmaf(p2, we.w, a2.w));
        a3.x = fmaf(s3, wc.x, fmaf(p3, we.x, a3.x));
        a3.y = fmaf(s3, wc.y, fmaf(p3, we.y, a3.y));
        a3.z = fmaf(s3, wc.z, fmaf(p3, we.z, a3.z));
        a3.w = fmaf(s3, wc.w, fmaf(p3, we.w, a3.w));
    }

    // bias + leaky relu
    float4 b1 = *(const float4*)&bc[j4 * 4];
    float4 b2 = *(const float4*)&be[j4 * 4];
    float4 bs = make_float4(b1.x + b2.x, b1.y + b2.y, b1.z + b2.z, b1.w + b2.w);

    float4 v[4];
    v[0] = make_float4(a0.x + bs.x, a0.y + bs.y, a0.z + bs.z, a0.w + bs.w);
    v[1] = make_float4(a1.x + bs.x, a1.y + bs.y, a1.z + bs.z, a1.w + bs.w);
    v[2] = make_float4(a2.x + bs.x, a2.y + bs.y, a2.z + bs.z, a2.w + bs.w);
    v[3] = make_float4(a3.x + bs.x, a3.y + bs.y, a3.z + bs.z, a3.w + bs.w);

    #pragma unroll
    for (int nn = 0; nn < 4; nn++) {
        v[nn].x = v[nn].x >= 0.f ? v[nn].x : 0.2f * v[nn].x;
        v[nn].y = v[nn].y >= 0.f ? v[nn].y : 0.2f * v[nn].y;
        v[nn].z = v[nn].z >= 0.f ? v[nn].z : 0.2f * v[nn].z;
        v[nn].w = v[nn].w >= 0.f ? v[nn].w : 0.2f * v[nn].w;
    }

    // per-node L2 norm: reduce across the 16 lanes holding this node's 64 dims
    #pragma unroll
    for (int nn = 0; nn < 4; nn++) {
        float4 x = v[nn];
        float q = x.x * x.x + x.y * x.y + x.z * x.z + x.w * x.w;
        q += __shfl_xor_sync(0xffffffffu, q, 8);
        q += __shfl_xor_sync(0xffffffffu, q, 4);
        q += __shfl_xor_sync(0xffffffffu, q, 2);
        q += __shfl_xor_sync(0xffffffffu, q, 1);
        float sc = 1.0f / fmaxf(sqrtf(q), 1e-12f);
        int node = nb + n0 + nn;
        if (node < N_NODES) {
            *(float4*)&g_emb[(size_t)node * DIM + j4 * 4] = x;  // unnormalized -> next layer
            float4 o = make_float4(x.x * sc, x.y * sc, x.z * sc, x.w * sc);
            *(float4*)&out_col[(size_t)node * OUT_COLS + j4 * 4] = o;
        }
    }
}

// ---------------------------------------------------------------------------
extern "C" void kernel_launch(void* const* d_in, const int* in_sizes, int n_in,
                              void* d_out, int out_size) {
    const int*   rows = (const int*)  d_in[0];
    const int*   cols = (const int*)  d_in[1];
    const float* vals = (const float*)d_in[2];
    const float* ue   = (const float*)d_in[3];
    const float* ie   = (const float*)d_in[4];
    const float* Wc   = (const float*)d_in[5];
    const float* bc   = (const float*)d_in[6];
    const float* We   = (const float*)d_in[7];
    const float* be   = (const float*)d_in[8];
    float* out = (float*)d_out;

    const int smem_bytes = (4096 * 2 + TILE_N * SROW * 2) * (int)sizeof(float); // 67584
    cudaFuncSetAttribute(dense_kernel, cudaFuncAttributeMaxDynamicSharedMemorySize, smem_bytes);

    const int vec_elems = N_NODES * (DIM / 4);           // 4.8M float4s
    concat_kernel<<<(vec_elems + 255) / 256, 256>>>(ue, ie, out);

    for (int l = 0; l < 3; l++) {
        spmm_kernel<<<(NNZ_E * 16 + 255) / 256, 256>>>(rows, cols, vals);
        dense_kernel<<<(N_NODES + TILE_N - 1) / TILE_N, 256, smem_bytes>>>(
            Wc + l * DIM * DIM, bc + l * DIM,
            We + l * DIM * DIM, be + l * DIM,
            out + (size_t)(l + 1) * DIM);
    }
}